// round 4
// baseline (speedup 1.0000x reference)
#include <cuda_runtime.h>

// Dilate (5x5 per-channel max filter, SAME padding) over (64, 384, 384, 3) fp32.
// Separable: vertical 5-max on a rolling 8-row register window (4 rows/batch,
// prefetch issued before the barrier), horizontal 5-max from a double-buffered
// shared row group with CLAMP-REPLICATED HALO float4s -> branch-free uniform
// horizontal pass (no divergent edge path, fewer registers).
// TH=48 -> 512 blocks = single wave at 4 blocks/SM.

#define IMG_H 384
#define IMG_W 384
#define IMG_C 3
#define ROWF (IMG_W * IMG_C)   // 1152 floats per row
#define ROWV (ROWF / 4)        // 288 float4 per row
#define TH   48                // output rows per block
#define U    4                 // rows per batch (one barrier per batch)
#define HAL  2                 // halo float4 on each side of a smem row

__device__ __forceinline__ float max5f(float a, float b, float c, float d, float e) {
    return fmaxf(fmaxf(fmaxf(a, b), fmaxf(c, d)), e);
}

__device__ __forceinline__ float4 vmax5(float4 a, float4 b, float4 c, float4 d, float4 e) {
    float4 r;
    r.x = max5f(a.x, b.x, c.x, d.x, e.x);
    r.y = max5f(a.y, b.y, c.y, d.y, e.y);
    r.z = max5f(a.z, b.z, c.z, d.z, e.z);
    r.w = max5f(a.w, b.w, c.w, d.w, e.w);
    return r;
}

__global__ void __launch_bounds__(ROWV, 4)
dilate5_kernel(const float* __restrict__ in, float* __restrict__ out) {
    // Double-buffered group of U vertical-max rows, each padded with 2 halo
    // float4 per side. 2*4*292*16B = 37,376 B.
    __shared__ __align__(16) float4 sbuf[2][U][ROWV + 2 * HAL];

    const int t   = threadIdx.x;            // float4 column 0..287
    const int img = blockIdx.y;
    const int y0  = blockIdx.x * TH;

    const float* base  = in  + (size_t)img * IMG_H * ROWF;
    float*       obase = out + (size_t)img * IMG_H * ROWF;

    auto loadrow = [&](int y) -> float4 {
        y = min(max(y, 0), IMG_H - 1);
        return __ldg(reinterpret_cast<const float4*>(base + (size_t)y * ROWF) + t);
    };

    // Rolling window of U+4 = 8 input rows: rows (y0+i-2) .. (y0+i+5).
    float4 r[U + 4];
    #pragma unroll
    for (int j = 0; j < U + 4; ++j) r[j] = loadrow(y0 - 2 + j);

    int buf = 0;

    for (int i = 0; i < TH; i += U) {
        // Vertical 5-tap max for U consecutive output rows -> smem.
        #pragma unroll
        for (int j = 0; j < U; ++j) {
            const float4 v = vmax5(r[j], r[j + 1], r[j + 2], r[j + 3], r[j + 4]);
            float4* sv = &sbuf[buf][j][HAL];
            sv[t] = v;
            // Clamp-replicated halos so the interior formula is exact at edges.
            // Left: floats j'<0 map to pixel x=0, same channel -> s[ch],
            // s[0..2] = v.x, v.y, v.z (thread 0 owns floats 0..3).
            if (t == 0) {
                sv[-2] = make_float4(v.y, v.z, v.x, v.y);  // j' = -8..-5
                sv[-1] = make_float4(v.z, v.x, v.y, v.z);  // j' = -4..-1
            }
            // Right: floats j'>=1152 map to pixel x=383 -> s[1149+ch],
            // s[1149..1151] = v.y, v.z, v.w (thread 287 owns floats 1148..1151).
            if (t == ROWV - 1) {
                sv[ROWV]     = make_float4(v.y, v.z, v.w, v.y);  // j' = 1152..1155
                sv[ROWV + 1] = make_float4(v.z, v.w, v.y, v.z);  // j' = 1156..1159
            }
        }

        // Window shift + prefetch for the NEXT batch, issued BEFORE the
        // barrier (loads are consumed a whole batch later).
        #pragma unroll
        for (int j = 0; j < 4; ++j) r[j] = r[j + U];
        if (i + U < TH) {
            #pragma unroll
            for (int j = 0; j < U; ++j) r[4 + j] = loadrow(y0 + i + U + 2 + j);
        }

        __syncthreads();

        // Horizontal 5-tap max (tap stride = 3 floats), branch-free.
        #pragma unroll
        for (int j = 0; j < U; ++j) {
            const float4* sv = &sbuf[buf][j][HAL];
            const float4 a = sv[t - 2];
            const float4 b = sv[t - 1];
            const float4 c = sv[t];
            const float4 d = sv[t + 1];
            const float4 e = sv[t + 2];
            float4 o;
            // float index jj = 4t+f; taps at jj-6, jj-3, jj, jj+3, jj+6
            o.x = max5f(a.z, b.y, c.x, c.w, d.z);
            o.y = max5f(a.w, b.z, c.y, d.x, d.w);
            o.z = max5f(b.x, b.w, c.z, d.y, e.x);
            o.w = max5f(b.y, c.x, c.w, d.z, e.y);
            reinterpret_cast<float4*>(obase + (size_t)(y0 + i + j) * ROWF)[t] = o;
        }

        buf ^= 1;
    }
}

extern "C" void kernel_launch(void* const* d_in, const int* in_sizes, int n_in,
                              void* d_out, int out_size) {
    (void)in_sizes; (void)n_in; (void)out_size;
    const float* images = (const float*)d_in[0];
    // d_in[1] is k (fixed at 5 for this problem)
    float* out = (float*)d_out;

    dim3 grid(IMG_H / TH, 64);
    dim3 block(ROWV);
    dilate5_kernel<<<grid, block>>>(images, out);
}

// round 5
// speedup vs baseline: 1.0332x; 1.0332x over previous
#include <cuda_runtime.h>

// Dilate (5x5 per-channel max filter, SAME padding) over (64, 384, 384, 3) fp32.
// R5 = R3 resource config (TH=32, 3 blocks/SM, 768 blocks, pre-barrier
// prefetch, tail guard) + R4's clamp-replicated halo (branch-free horizontal
// pass). R4 showed that capping regs at 56 for 4 blocks/SM causes spills and
// a net regression; occupancy is not the binding resource here.

#define IMG_H 384
#define IMG_W 384
#define IMG_C 3
#define ROWF (IMG_W * IMG_C)   // 1152 floats per row
#define ROWV (ROWF / 4)        // 288 float4 per row
#define TH   32                // output rows per block
#define U    4                 // rows per batch (one barrier per batch)
#define HAL  2                 // halo float4 on each side of a smem row

__device__ __forceinline__ float max5f(float a, float b, float c, float d, float e) {
    return fmaxf(fmaxf(fmaxf(a, b), fmaxf(c, d)), e);
}

__device__ __forceinline__ float4 vmax5(float4 a, float4 b, float4 c, float4 d, float4 e) {
    float4 r;
    r.x = max5f(a.x, b.x, c.x, d.x, e.x);
    r.y = max5f(a.y, b.y, c.y, d.y, e.y);
    r.z = max5f(a.z, b.z, c.z, d.z, e.z);
    r.w = max5f(a.w, b.w, c.w, d.w, e.w);
    return r;
}

__global__ void __launch_bounds__(ROWV, 3)
dilate5_kernel(const float* __restrict__ in, float* __restrict__ out) {
    // Double-buffered group of U vertical-max rows, each padded with 2 halo
    // float4 per side. 2*4*292*16B = 37,376 B.
    __shared__ __align__(16) float4 sbuf[2][U][ROWV + 2 * HAL];

    const int t   = threadIdx.x;            // float4 column 0..287
    const int img = blockIdx.y;
    const int y0  = blockIdx.x * TH;

    const float* base  = in  + (size_t)img * IMG_H * ROWF;
    float*       obase = out + (size_t)img * IMG_H * ROWF;

    auto loadrow = [&](int y) -> float4 {
        y = min(max(y, 0), IMG_H - 1);
        return __ldg(reinterpret_cast<const float4*>(base + (size_t)y * ROWF) + t);
    };

    // Rolling window of U+4 = 8 input rows: rows (y0+i-2) .. (y0+i+5).
    float4 r[U + 4];
    #pragma unroll
    for (int j = 0; j < U + 4; ++j) r[j] = loadrow(y0 - 2 + j);

    int buf = 0;

    for (int i = 0; i < TH; i += U) {
        // Vertical 5-tap max for U consecutive output rows -> smem.
        #pragma unroll
        for (int j = 0; j < U; ++j) {
            const float4 v = vmax5(r[j], r[j + 1], r[j + 2], r[j + 3], r[j + 4]);
            float4* sv = &sbuf[buf][j][HAL];
            sv[t] = v;
            // Clamp-replicated halos so the interior formula is exact at edges.
            // Left: out-of-range floats map to pixel x=0, same channel;
            // s[0..2] = v.x, v.y, v.z (thread 0 owns floats 0..3).
            if (t == 0) {
                sv[-2] = make_float4(v.y, v.z, v.x, v.y);  // floats -8..-5
                sv[-1] = make_float4(v.z, v.x, v.y, v.z);  // floats -4..-1
            }
            // Right: out-of-range floats map to pixel x=383;
            // s[1149..1151] = v.y, v.z, v.w (thread 287 owns floats 1148..1151).
            if (t == ROWV - 1) {
                sv[ROWV]     = make_float4(v.y, v.z, v.w, v.y);  // floats 1152..1155
                sv[ROWV + 1] = make_float4(v.z, v.w, v.y, v.z);  // floats 1156..1159
            }
        }

        // Window shift + prefetch for the NEXT batch, issued BEFORE the
        // barrier (loads are consumed a whole batch later -> latency hidden
        // behind barrier + horizontal pass).
        #pragma unroll
        for (int j = 0; j < 4; ++j) r[j] = r[j + U];
        if (i + U < TH) {
            #pragma unroll
            for (int j = 0; j < U; ++j) r[4 + j] = loadrow(y0 + i + U + 2 + j);
        }

        __syncthreads();

        // Horizontal 5-tap max (tap stride = 3 floats), branch-free.
        #pragma unroll
        for (int j = 0; j < U; ++j) {
            const float4* sv = &sbuf[buf][j][HAL];
            const float4 a = sv[t - 2];
            const float4 b = sv[t - 1];
            const float4 c = sv[t];
            const float4 d = sv[t + 1];
            const float4 e = sv[t + 2];
            float4 o;
            // float index jj = 4t+f; taps at jj-6, jj-3, jj, jj+3, jj+6
            o.x = max5f(a.z, b.y, c.x, c.w, d.z);
            o.y = max5f(a.w, b.z, c.y, d.x, d.w);
            o.z = max5f(b.x, b.w, c.z, d.y, e.x);
            o.w = max5f(b.y, c.x, c.w, d.z, e.y);
            reinterpret_cast<float4*>(obase + (size_t)(y0 + i + j) * ROWF)[t] = o;
        }

        buf ^= 1;
    }
}

extern "C" void kernel_launch(void* const* d_in, const int* in_sizes, int n_in,
                              void* d_out, int out_size) {
    (void)in_sizes; (void)n_in; (void)out_size;
    const float* images = (const float*)d_in[0];
    // d_in[1] is k (fixed at 5 for this problem)
    float* out = (float*)d_out;

    dim3 grid(IMG_H / TH, 64);
    dim3 block(ROWV);
    dilate5_kernel<<<grid, block>>>(images, out);
}

// round 6
// speedup vs baseline: 1.1895x; 1.1513x over previous
#include <cuda_runtime.h>

// Dilate (5x5 per-channel max filter, SAME padding) over (64, 384, 384, 3) fp32.
// R6: single-wave grid (448 blocks = 7 row-chunks x 64 images, chunk = 56/48
// rows), LDS.64 for the +-2 horizontal taps (only 2 floats of each are used),
// factored shared submax for o.x/o.w. Keeps R3's proven config: TH rows
// per block streamed in U=4 batches, rolling 8-row register window,
// pre-barrier prefetch, clamp-replicated halo, 3 blocks/SM.

#define IMG_H 384
#define IMG_W 384
#define IMG_C 3
#define ROWF (IMG_W * IMG_C)   // 1152 floats per row
#define ROWV (ROWF / 4)        // 288 float4 per row
#define U    4                 // rows per batch (one barrier per batch)
#define HAL  2                 // halo float4 on each side of a smem row
#define CHUNK 56               // rows per block (last chunk: 48)

__device__ __forceinline__ float max5f(float a, float b, float c, float d, float e) {
    return fmaxf(fmaxf(fmaxf(a, b), fmaxf(c, d)), e);
}

__device__ __forceinline__ float4 vmax5(float4 a, float4 b, float4 c, float4 d, float4 e) {
    float4 r;
    r.x = max5f(a.x, b.x, c.x, d.x, e.x);
    r.y = max5f(a.y, b.y, c.y, d.y, e.y);
    r.z = max5f(a.z, b.z, c.z, d.z, e.z);
    r.w = max5f(a.w, b.w, c.w, d.w, e.w);
    return r;
}

__global__ void __launch_bounds__(ROWV, 3)
dilate5_kernel(const float* __restrict__ in, float* __restrict__ out) {
    // Double-buffered group of U vertical-max rows + 2 halo float4 per side.
    __shared__ __align__(16) float4 sbuf[2][U][ROWV + 2 * HAL];

    const int t   = threadIdx.x;            // float4 column 0..287
    const int img = blockIdx.y;
    const int bx  = blockIdx.x;             // 0..6 row-chunk
    const int y0  = bx * CHUNK;
    const int TH  = (bx == 6) ? (IMG_H - 6 * CHUNK) : CHUNK;   // 48 or 56

    const float* base  = in  + (size_t)img * IMG_H * ROWF;
    float*       obase = out + (size_t)img * IMG_H * ROWF;

    auto loadrow = [&](int y) -> float4 {
        y = min(max(y, 0), IMG_H - 1);
        return __ldg(reinterpret_cast<const float4*>(base + (size_t)y * ROWF) + t);
    };

    // Rolling window of U+4 = 8 input rows: rows (y0+i-2) .. (y0+i+5).
    float4 r[U + 4];
    #pragma unroll
    for (int j = 0; j < U + 4; ++j) r[j] = loadrow(y0 - 2 + j);

    int buf = 0;

    for (int i = 0; i < TH; i += U) {
        // Vertical 5-tap max for U consecutive output rows -> smem.
        #pragma unroll
        for (int j = 0; j < U; ++j) {
            const float4 v = vmax5(r[j], r[j + 1], r[j + 2], r[j + 3], r[j + 4]);
            float4* sv = &sbuf[buf][j][HAL];
            sv[t] = v;
            // Clamp-replicated halos: out-of-range taps map to edge pixel,
            // same channel. Left edge channels = v.x,v.y,v.z of thread 0;
            // right edge channels = v.y,v.z,v.w of thread 287.
            if (t == 0) {
                sv[-2] = make_float4(v.y, v.z, v.x, v.y);
                sv[-1] = make_float4(v.z, v.x, v.y, v.z);
            }
            if (t == ROWV - 1) {
                sv[ROWV]     = make_float4(v.y, v.z, v.w, v.y);
                sv[ROWV + 1] = make_float4(v.z, v.w, v.y, v.z);
            }
        }

        // Window shift + prefetch for the NEXT batch before the barrier
        // (consumed a whole batch later -> DRAM latency hidden).
        #pragma unroll
        for (int j = 0; j < 4; ++j) r[j] = r[j + U];
        if (i + U < TH) {
            #pragma unroll
            for (int j = 0; j < U; ++j) r[4 + j] = loadrow(y0 + i + U + 2 + j);
        }

        __syncthreads();

        // Horizontal 5-tap max (tap stride = 3 floats), branch-free.
        // Only a.z,a.w and e.x,e.y of the +-2 taps are used -> LDS.64.
        #pragma unroll
        for (int j = 0; j < U; ++j) {
            const float4* sv = &sbuf[buf][j][HAL];
            const float2* s2 = reinterpret_cast<const float2*>(sv);
            const float2 azw = s2[2 * (t - 2) + 1];   // a.z, a.w
            const float4 b   = sv[t - 1];
            const float4 c   = sv[t];
            const float4 d   = sv[t + 1];
            const float2 exy = s2[2 * (t + 2)];       // e.x, e.y
            float4 o;
            // float index jj = 4t+f; taps at jj-6, jj-3, jj, jj+3, jj+6.
            // o.x and o.w share the 4-tap submax m.
            const float m = fmaxf(fmaxf(b.y, c.x), fmaxf(c.w, d.z));
            o.x = fmaxf(m, azw.x);
            o.w = fmaxf(m, exy.y);
            o.y = max5f(azw.y, b.z, c.y, d.x, d.w);
            o.z = max5f(b.x, b.w, c.z, d.y, exy.x);
            reinterpret_cast<float4*>(obase + (size_t)(y0 + i + j) * ROWF)[t] = o;
        }

        buf ^= 1;
    }
}

extern "C" void kernel_launch(void* const* d_in, const int* in_sizes, int n_in,
                              void* d_out, int out_size) {
    (void)in_sizes; (void)n_in; (void)out_size;
    const float* images = (const float*)d_in[0];
    // d_in[1] is k (fixed at 5 for this problem)
    float* out = (float*)d_out;

    dim3 grid(7, 64);        // 448 blocks = one full wave at 3 blocks/SM
    dim3 block(ROWV);
    dilate5_kernel<<<grid, block>>>(images, out);
}